// round 2
// baseline (speedup 1.0000x reference)
#include <cuda_runtime.h>
#include <cuda_bf16.h>

// DAGNN layer: deg-norm, 10x SpMM (CSR gather), fused sigmoid-attention pooling.
// N=100000, D=64, E=1600000, K=10 (fixed by problem).

#define MAX_N 100000
#define MAX_E 1600000
#define D 64
#define KHOPS 10

// ---------------- device scratch (static: allocation-free rule) ----------------
__device__ float g_bufA[MAX_N * D];     // ping  (holds g = norm*h)
__device__ float g_bufB[MAX_N * D];     // pong
__device__ float g_norm[MAX_N];
__device__ int   g_deg[MAX_N];
__device__ int   g_cursor[MAX_N];
__device__ int   g_rowptr[MAX_N + 1];
__device__ int   g_csr_src[MAX_E];
__device__ int   g_idx64;               // 1 if src/dst are int64, 0 if int32

// ---------------- dtype probe (graph-capturable, no host sync) ----------------
__global__ void detect_kernel(const void* __restrict__ dst) {
    // Examine first 1024 32-bit words (safe for either dtype: int32 buffer has
    // 1.6M words, int64 buffer has 3.2M words). If underlying int64 with values
    // < 2^31, all odd words are zero.
    const unsigned* w = (const unsigned*)dst;
    int allzero = 1;
    for (int i = 1; i < 1024; i += 2)
        if (w[i] != 0u) { allzero = 0; break; }
    g_idx64 = allzero;
}

__device__ __forceinline__ int read_idx(const void* p, int i, int is64) {
    if (is64) return (int)((const long long*)p)[i];
    return ((const int*)p)[i];
}

// ---------------- CSR build ----------------
__global__ void init_kernel(int n) {
    for (int i = blockIdx.x * blockDim.x + threadIdx.x; i < n;
         i += gridDim.x * blockDim.x) {
        g_deg[i] = 0;
        g_cursor[i] = 0;
    }
}

__global__ void deg_kernel(const void* __restrict__ dst, int e) {
    int is64 = g_idx64;
    for (int i = blockIdx.x * blockDim.x + threadIdx.x; i < e;
         i += gridDim.x * blockDim.x) {
        atomicAdd(&g_deg[read_idx(dst, i, is64)], 1);
    }
}

__global__ void norm_kernel(int n) {
    for (int i = blockIdx.x * blockDim.x + threadIdx.x; i < n;
         i += gridDim.x * blockDim.x) {
        float d = (float)g_deg[i];
        g_norm[i] = rsqrtf(fmaxf(d, 1.0f));
    }
}

// single-block exclusive scan of degrees -> rowptr
__global__ void scan_kernel(int n) {
    __shared__ int part[1024];
    int t = threadIdx.x;
    int chunk = (n + 1023) / 1024;
    int beg = t * chunk;
    int end = beg + chunk; if (end > n) end = n;
    if (beg > n) beg = n;
    int s = 0;
    for (int i = beg; i < end; ++i) s += g_deg[i];
    part[t] = s;
    __syncthreads();
    if (t == 0) {
        int acc = 0;
        for (int i = 0; i < 1024; ++i) { int v = part[i]; part[i] = acc; acc += v; }
    }
    __syncthreads();
    int acc = part[t];
    for (int i = beg; i < end; ++i) { g_rowptr[i] = acc; acc += g_deg[i]; }
    if (t == 1023) {
        // total = part[1023] + its own (empty or not) sum
        g_rowptr[n] = acc + (beg >= end ? 0 : 0);  // acc already includes own range
        // if this thread's range was empty, acc == part[1023] == total
    }
    if (end == n && beg < n) g_rowptr[n] = acc;  // thread owning the tail also writes
}

__global__ void fill_kernel(const void* __restrict__ src,
                            const void* __restrict__ dst, int e) {
    int is64 = g_idx64;
    for (int i = blockIdx.x * blockDim.x + threadIdx.x; i < e;
         i += gridDim.x * blockDim.x) {
        int d = read_idx(dst, i, is64);
        int p = atomicAdd(&g_cursor[d], 1);
        g_csr_src[g_rowptr[d] + p] = read_idx(src, i, is64);
    }
}

// ---------------- hop 0: init out with sigma(f.s)*f, g = norm*f ----------------
__global__ void prep_kernel(const float* __restrict__ feat,
                            const float* __restrict__ s,
                            float* __restrict__ out,
                            float* __restrict__ g_out, int n) {
    int warp = (blockIdx.x * blockDim.x + threadIdx.x) >> 5;
    int lane = threadIdx.x & 31;
    if (warp >= n) return;
    int d2 = lane * 2;
    size_t base = (size_t)warp * D + d2;
    float2 f = *(const float2*)(feat + base);
    float2 sv = *(const float2*)(s + d2);
    float dot = f.x * sv.x + f.y * sv.y;
    #pragma unroll
    for (int off = 16; off; off >>= 1) dot += __shfl_xor_sync(0xffffffffu, dot, off);
    float sig = 1.0f / (1.0f + __expf(-dot));
    float2 o; o.x = sig * f.x; o.y = sig * f.y;
    *(float2*)(out + base) = o;
    float nm = g_norm[warp];
    float2 go; go.x = nm * f.x; go.y = nm * f.y;
    *(float2*)(g_out + base) = go;
}

// ---------------- one hop: gather-sum, scale, pool, rescale ----------------
__global__ void hop_kernel(const float* __restrict__ g_in,
                           float* __restrict__ g_out,
                           float* __restrict__ out,
                           const float* __restrict__ s, int n) {
    int warp = (blockIdx.x * blockDim.x + threadIdx.x) >> 5;
    int lane = threadIdx.x & 31;
    if (warp >= n) return;
    int beg = g_rowptr[warp];
    int end = g_rowptr[warp + 1];
    int d2 = lane * 2;
    float a0 = 0.0f, a1 = 0.0f;
    for (int j = beg; j < end; ++j) {
        int sn = g_csr_src[j];                       // broadcast within warp
        float2 v = *(const float2*)(g_in + (size_t)sn * D + d2);  // 256B coalesced
        a0 += v.x; a1 += v.y;
    }
    float nm = g_norm[warp];
    float h0 = a0 * nm, h1 = a1 * nm;                // h_t
    float2 sv = *(const float2*)(s + d2);
    float dot = h0 * sv.x + h1 * sv.y;
    #pragma unroll
    for (int off = 16; off; off >>= 1) dot += __shfl_xor_sync(0xffffffffu, dot, off);
    float sig = 1.0f / (1.0f + __expf(-dot));
    size_t base = (size_t)warp * D + d2;
    float2* op = (float2*)(out + base);
    float2 o = *op;
    o.x += sig * h0; o.y += sig * h1;
    *op = o;
    float2 go; go.x = nm * h0; go.y = nm * h1;       // g_{t} for next hop
    *(float2*)(g_out + base) = go;
}

// ---------------- launch ----------------
extern "C" void kernel_launch(void* const* d_in, const int* in_sizes, int n_in,
                              void* d_out, int out_size) {
    const float* feat = (const float*)d_in[0];
    const float* s    = (const float*)d_in[1];
    const void*  src  = d_in[2];
    const void*  dst  = d_in[3];
    float* out = (float*)d_out;

    int n = in_sizes[0] / D;
    int e = in_sizes[2];

    // device-symbol addresses (resolved host-side, no allocation)
    float *dA, *dB;
    cudaGetSymbolAddress((void**)&dA, g_bufA);
    cudaGetSymbolAddress((void**)&dB, g_bufB);

    const int T = 256;
    int blkN = (n + T - 1) / T;
    int blkE = (e + T - 1) / T; if (blkE > 2048) blkE = 2048;
    int blkW = (int)(((size_t)n * 32 + T - 1) / T);   // one warp per node

    detect_kernel<<<1, 1>>>(dst);
    init_kernel<<<blkN, T>>>(n);
    deg_kernel<<<blkE, T>>>(dst, e);
    norm_kernel<<<blkN, T>>>(n);
    scan_kernel<<<1, 1024>>>(n);
    fill_kernel<<<blkE, T>>>(src, dst, e);

    prep_kernel<<<blkW, T>>>(feat, s, out, dA, n);

    float* gin = dA;
    float* gout = dB;
    for (int t = 0; t < KHOPS; ++t) {
        hop_kernel<<<blkW, T>>>(gin, gout, out, s, n);
        float* tmp = gin; gin = gout; gout = tmp;
    }
    (void)n_in; (void)out_size;
}

// round 3
// speedup vs baseline: 1.0700x; 1.0700x over previous
#include <cuda_runtime.h>
#include <cuda_fp16.h>

// DAGNN layer: deg-norm, 10x SpMM (CSR gather, fp16 hop buffers, fp32 accum),
// fused sigmoid-attention pooling. N=100000, D=64, E=1600000, K=10.

#define MAX_N 100000
#define MAX_E 1600000
#define D 64
#define KHOPS 10

// ---------------- device scratch (static: allocation-free rule) ----------------
__device__ __half g_bufA[MAX_N * D];    // ping  (holds g = norm*h, fp16)
__device__ __half g_bufB[MAX_N * D];    // pong
__device__ float  g_norm[MAX_N];
__device__ int    g_deg[MAX_N];
__device__ int    g_cursor[MAX_N];
__device__ int    g_rowptr[MAX_N + 1];
__device__ int    g_csr_src[MAX_E];
__device__ int    g_idx64;              // 1 if src/dst are int64, 0 if int32

// ---------------- dtype probe (parallel, graph-capturable) ----------------
__global__ void detect_kernel(const void* __restrict__ dst) {
    // Check odd 32-bit words of the first 2048 words. If the buffer is int64
    // with values < 2^31, all odd words are zero; if int32, they are random ids.
    const unsigned* w = (const unsigned*)dst;
    int t = threadIdx.x;
    int ok = (w[2 * t + 1] == 0u) ? 1 : 0;
    int all = __syncthreads_and(ok);
    if (t == 0) g_idx64 = all;
}

__device__ __forceinline__ int read_idx(const void* p, int i, int is64) {
    if (is64) return (int)((const long long*)p)[i];
    return ((const int*)p)[i];
}

// ---------------- CSR build ----------------
__global__ void init_kernel(int n) {
    for (int i = blockIdx.x * blockDim.x + threadIdx.x; i < n;
         i += gridDim.x * blockDim.x) {
        g_deg[i] = 0;
        g_cursor[i] = 0;
    }
}

__global__ void deg_kernel(const void* __restrict__ dst, int e) {
    int is64 = g_idx64;
    for (int i = blockIdx.x * blockDim.x + threadIdx.x; i < e;
         i += gridDim.x * blockDim.x) {
        atomicAdd(&g_deg[read_idx(dst, i, is64)], 1);
    }
}

__global__ void norm_kernel(int n) {
    for (int i = blockIdx.x * blockDim.x + threadIdx.x; i < n;
         i += gridDim.x * blockDim.x) {
        float d = (float)g_deg[i];
        g_norm[i] = rsqrtf(fmaxf(d, 1.0f));
    }
}

// single-block exclusive scan of degrees -> rowptr
__global__ void scan_kernel(int n) {
    __shared__ int part[1024];
    int t = threadIdx.x;
    int chunk = (n + 1023) / 1024;
    int beg = t * chunk;
    int end = beg + chunk;
    if (beg > n) beg = n;
    if (end > n) end = n;
    int s = 0;
    for (int i = beg; i < end; ++i) s += g_deg[i];
    part[t] = s;
    __syncthreads();
    if (t == 0) {
        int acc = 0;
        for (int i = 0; i < 1024; ++i) { int v = part[i]; part[i] = acc; acc += v; }
    }
    __syncthreads();
    int acc = part[t];
    for (int i = beg; i < end; ++i) { g_rowptr[i] = acc; acc += g_deg[i]; }
    if (t == 1023) g_rowptr[n] = acc;   // last thread's acc == grand total
}

__global__ void fill_kernel(const void* __restrict__ src,
                            const void* __restrict__ dst, int e) {
    int is64 = g_idx64;
    for (int i = blockIdx.x * blockDim.x + threadIdx.x; i < e;
         i += gridDim.x * blockDim.x) {
        int d = read_idx(dst, i, is64);
        int p = atomicAdd(&g_cursor[d], 1);
        g_csr_src[g_rowptr[d] + p] = read_idx(src, i, is64);
    }
}

// ---------------- hop 0: init out with sigma(f.s)*f, g = norm*f (fp16) --------
__global__ void prep_kernel(const float* __restrict__ feat,
                            const float* __restrict__ s,
                            float* __restrict__ out,
                            __half* __restrict__ g_out, int n) {
    int warp = (blockIdx.x * blockDim.x + threadIdx.x) >> 5;
    int lane = threadIdx.x & 31;
    if (warp >= n) return;
    int d2 = lane * 2;
    size_t base = (size_t)warp * D + d2;
    float2 f = *(const float2*)(feat + base);
    float2 sv = *(const float2*)(s + d2);
    float dot = f.x * sv.x + f.y * sv.y;
    #pragma unroll
    for (int off = 16; off; off >>= 1) dot += __shfl_xor_sync(0xffffffffu, dot, off);
    float sig = 1.0f / (1.0f + __expf(-dot));
    float2 o; o.x = sig * f.x; o.y = sig * f.y;
    *(float2*)(out + base) = o;
    float nm = g_norm[warp];
    float2 go; go.x = nm * f.x; go.y = nm * f.y;
    *(__half2*)(g_out + base) = __float22half2_rn(go);
}

// ---------------- one hop: gather-sum (fp16 in, fp32 accum), pool -------------
__global__ void hop_kernel(const __half* __restrict__ g_in,
                           __half* __restrict__ g_out,
                           float* __restrict__ out,
                           const float* __restrict__ s, int n) {
    int warp = (blockIdx.x * blockDim.x + threadIdx.x) >> 5;
    int lane = threadIdx.x & 31;
    if (warp >= n) return;
    int beg = g_rowptr[warp];
    int end = g_rowptr[warp + 1];
    int d2 = lane * 2;
    float a0 = 0.0f, a1 = 0.0f;
    #pragma unroll 4
    for (int j = beg; j < end; ++j) {
        int sn = g_csr_src[j];                                // warp broadcast
        __half2 v = *(const __half2*)(g_in + (size_t)sn * D + d2);  // 128B/edge
        float2 vf = __half22float2(v);
        a0 += vf.x; a1 += vf.y;
    }
    float nm = g_norm[warp];
    float h0 = a0 * nm, h1 = a1 * nm;                // h_t (fp32)
    float2 sv = *(const float2*)(s + d2);
    float dot = h0 * sv.x + h1 * sv.y;
    #pragma unroll
    for (int off = 16; off; off >>= 1) dot += __shfl_xor_sync(0xffffffffu, dot, off);
    float sig = 1.0f / (1.0f + __expf(-dot));
    size_t base = (size_t)warp * D + d2;
    float2* op = (float2*)(out + base);
    float2 o = *op;
    o.x += sig * h0; o.y += sig * h1;
    *op = o;
    float2 go; go.x = nm * h0; go.y = nm * h1;       // g_t for next hop
    *(__half2*)(g_out + base) = __float22half2_rn(go);
}

// ---------------- launch ----------------
extern "C" void kernel_launch(void* const* d_in, const int* in_sizes, int n_in,
                              void* d_out, int out_size) {
    const float* feat = (const float*)d_in[0];
    const float* s    = (const float*)d_in[1];
    const void*  src  = d_in[2];
    const void*  dst  = d_in[3];
    float* out = (float*)d_out;

    int n = in_sizes[0] / D;
    int e = in_sizes[2];

    __half *dA, *dB;
    cudaGetSymbolAddress((void**)&dA, g_bufA);
    cudaGetSymbolAddress((void**)&dB, g_bufB);

    const int T = 256;
    int blkN = (n + T - 1) / T;
    int blkE = (e + T - 1) / T; if (blkE > 2048) blkE = 2048;
    int blkW = (int)(((size_t)n * 32 + T - 1) / T);   // one warp per node

    detect_kernel<<<1, 256>>>(dst);
    init_kernel<<<blkN, T>>>(n);
    deg_kernel<<<blkE, T>>>(dst, e);
    norm_kernel<<<blkN, T>>>(n);
    scan_kernel<<<1, 1024>>>(n);
    fill_kernel<<<blkE, T>>>(src, dst, e);

    prep_kernel<<<blkW, T>>>(feat, s, out, dA, n);

    __half* gin = dA;
    __half* gout = dB;
    for (int t = 0; t < KHOPS; ++t) {
        hop_kernel<<<blkW, T>>>(gin, gout, out, s, n);
        __half* tmp = gin; gin = gout; gout = tmp;
    }
    (void)n_in; (void)out_size;
}